// round 7
// baseline (speedup 1.0000x reference)
#include <cuda_runtime.h>
#include <cstdint>

#define D_DIM   768
#define K_CL    16
#define TPB     128         // 4 warps; TPB*EPT = D_DIM
#define EPT     6           // elements per thread (3 float2)
#define RR      8           // rows per block
#define NVAL    18          // 16 dots + sum + sumsq
#define PS      36          // plane stride (floats): 144B, 16B-aligned, conflict-free

typedef unsigned long long u64;

__device__ float g_c2[K_CL];

// ---- packed f32x2 helpers (sm_103a FFMA2 path; ptxas won't auto-fuse) ----
__device__ __forceinline__ u64 pack2(float lo, float hi) {
    u64 d; asm("mov.b64 %0, {%1, %2};" : "=l"(d) : "f"(lo), "f"(hi)); return d;
}
__device__ __forceinline__ float2 unpk(u64 v) {
    float2 r; asm("mov.b64 {%0, %1}, %2;" : "=f"(r.x), "=f"(r.y) : "l"(v)); return r;
}
__device__ __forceinline__ u64 fma2(u64 a, u64 b, u64 c) {
    u64 d; asm("fma.rn.f32x2 %0, %1, %2, %3;" : "=l"(d) : "l"(a), "l"(b), "l"(c)); return d;
}
__device__ __forceinline__ u64 mul2(u64 a, u64 b) {
    u64 d; asm("mul.rn.f32x2 %0, %1, %2;" : "=l"(d) : "l"(a), "l"(b)); return d;
}
__device__ __forceinline__ u64 add2(u64 a, u64 b) {
    u64 d; asm("add.rn.f32x2 %0, %1, %2;" : "=l"(d) : "l"(a), "l"(b)); return d;
}

// Precompute ||c_k||^2 once per launch sequence. 16 warps, one per centroid.
__global__ void c2_kernel(const float* __restrict__ cen) {
    int k = threadIdx.x >> 5;
    int lane = threadIdx.x & 31;
    float s = 0.f;
    #pragma unroll
    for (int i = 0; i < D_DIM / 32; i++) {
        float v = cen[k * D_DIM + lane + i * 32];
        s = fmaf(v, v, s);
    }
    #pragma unroll
    for (int o = 16; o > 0; o >>= 1) s += __shfl_xor_sync(0xffffffffu, s, o);
    if (lane == 0) g_c2[k] = s;
}

__global__ __launch_bounds__(TPB, 5) void sln_kernel(
    const float* __restrict__ x, const float* __restrict__ wts,
    const float* __restrict__ bia, const float* __restrict__ cen,
    float* __restrict__ out, float* __restrict__ bkt, int write_bkt)
{
    __shared__ float part[RR * NVAL * PS];   // 20.7 KB: 4-lane-pre-reduced partials
    __shared__ float tot[RR][NVAL + 2];
    __shared__ float c2s[K_CL];

    const int u = threadIdx.x;
    const int lane = u & 31;
    const int col = u >> 2;                  // 0..31 after 4-lane group reduction
    const long long base_row = (long long)blockIdx.x * RR;

    if (u < K_CL) c2s[u] = g_c2[u];

    // ---- load x in row-pairs; sum/sumsq reduced+stored immediately (short liveness) ----
    u64 xp[RR][3];
    #pragma unroll
    for (int ri = 0; ri < RR / 2; ri++) {
        float sm2[2], sq2[2];
        #pragma unroll
        for (int h = 0; h < 2; h++) {
            int r = 2 * ri + h;
            const u64* xr = (const u64*)(x + (base_row + r) * D_DIM + u * EPT);
            xp[r][0] = xr[0]; xp[r][1] = xr[1]; xp[r][2] = xr[2];
            u64 s2 = add2(xp[r][0], add2(xp[r][1], xp[r][2]));
            u64 q2 = mul2(xp[r][0], xp[r][0]);
            q2 = fma2(xp[r][1], xp[r][1], q2);
            q2 = fma2(xp[r][2], xp[r][2], q2);
            float2 ts = unpk(s2), tq = unpk(q2);
            sm2[h] = ts.x + ts.y;
            sq2[h] = tq.x + tq.y;
        }
        u64 sp = pack2(sm2[0], sm2[1]);
        u64 qp = pack2(sq2[0], sq2[1]);
        sp = add2(sp, __shfl_down_sync(0xffffffffu, sp, 1));
        sp = add2(sp, __shfl_down_sync(0xffffffffu, sp, 2));
        qp = add2(qp, __shfl_down_sync(0xffffffffu, qp, 1));
        qp = add2(qp, __shfl_down_sync(0xffffffffu, qp, 2));
        if ((lane & 3) == 0) {
            float2 a = unpk(sp), b = unpk(qp);
            part[((2 * ri)     * NVAL + 16) * PS + col] = a.x;
            part[((2 * ri + 1) * NVAL + 16) * PS + col] = a.y;
            part[((2 * ri)     * NVAL + 17) * PS + col] = b.x;
            part[((2 * ri + 1) * NVAL + 17) * PS + col] = b.y;
        }
    }

    // ---- 16 centroid dot partials; centroid chunk loaded once, reused for 8 rows ----
    #pragma unroll
    for (int k = 0; k < K_CL; k++) {
        const u64* cr = (const u64*)(cen + k * D_DIM + u * EPT);
        u64 c0 = cr[0], c1 = cr[1], c2p = cr[2];
        #pragma unroll
        for (int ri = 0; ri < RR / 2; ri++) {
            u64 a0 = mul2(xp[2 * ri][0], c0);
            a0 = fma2(xp[2 * ri][1], c1, a0);
            a0 = fma2(xp[2 * ri][2], c2p, a0);
            u64 a1 = mul2(xp[2 * ri + 1][0], c0);
            a1 = fma2(xp[2 * ri + 1][1], c1, a1);
            a1 = fma2(xp[2 * ri + 1][2], c2p, a1);
            float2 t0 = unpk(a0), t1 = unpk(a1);
            u64 dp = pack2(t0.x + t0.y, t1.x + t1.y);
            dp = add2(dp, __shfl_down_sync(0xffffffffu, dp, 1));
            dp = add2(dp, __shfl_down_sync(0xffffffffu, dp, 2));
            if ((lane & 3) == 0) {
                float2 t = unpk(dp);
                part[((2 * ri)     * NVAL + k) * PS + col] = t.x;
                part[((2 * ri + 1) * NVAL + k) * PS + col] = t.y;
            }
        }
    }
    __syncthreads();

    // ---- stage 2: 144 jobs (18 vals x 8 rows), each sums 32 floats via LDS.128 ----
    for (int j = u; j < RR * NVAL; j += TPB) {
        const float4* p = (const float4*)(part + j * PS);
        float s0 = 0.f, s1 = 0.f;
        #pragma unroll
        for (int i = 0; i < 8; i += 2) {
            float4 a = p[i], b = p[i + 1];
            s0 += (a.x + a.y) + (a.z + a.w);
            s1 += (b.x + b.y) + (b.z + b.w);
        }
        tot[j / NVAL][j % NVAL] = s0 + s1;
    }
    __syncthreads();

    // ---- epilogue: per-row stats + argmin from tot (broadcast LDS), packed affine ----
    #pragma unroll
    for (int r = 0; r < RR; r++) {
        float s = tot[r][16], q = tot[r][17];
        float m = s * (1.0f / D_DIM);
        float var = q * (1.0f / D_DIM) - m * m;
        float rstd = rsqrtf(var + 1e-5f);
        float best = 3.4e38f; int sel = 0;
        #pragma unroll
        for (int k = 0; k < K_CL; k++) {
            float dist = q - 2.0f * tot[r][k] + c2s[k];   // same formula as reference
            if (dist < best) { best = dist; sel = k; }     // strict < = first-min tie-break
        }

        const u64* wr = (const u64*)(wts + sel * D_DIM + u * EPT);
        const u64* br = (const u64*)(bia + sel * D_DIM + u * EPT);
        u64 w0 = wr[0], w1 = wr[1], w2 = wr[2];
        u64 b0 = br[0], b1 = br[1], b2 = br[2];
        u64 nm = pack2(-m, -m);
        u64 rs = pack2(rstd, rstd);
        u64 o0 = fma2(mul2(add2(xp[r][0], nm), rs), w0, b0);
        u64 o1 = fma2(mul2(add2(xp[r][1], nm), rs), w1, b1);
        u64 o2 = fma2(mul2(add2(xp[r][2], nm), rs), w2, b2);
        u64* orow = (u64*)(out + (base_row + r) * D_DIM + u * EPT);
        orow[0] = o0; orow[1] = o1; orow[2] = o2;

        if (write_bkt && u == 0) bkt[base_row + r] = (float)sel;
    }
}

extern "C" void kernel_launch(void* const* d_in, const int* in_sizes, int n_in,
                              void* d_out, int out_size) {
    const float* x = (const float*)d_in[0];   // [B,S,D] f32
    const float* w = (const float*)d_in[1];   // [K,D]
    const float* b = (const float*)d_in[2];   // [K,D]
    const float* c = (const float*)d_in[3];   // [K,D]
    float* out = (float*)d_out;

    int rows = in_sizes[0] / D_DIM;           // 32768
    int wb = (out_size >= rows * D_DIM + rows) ? 1 : 0;
    float* bkt = out + (size_t)rows * D_DIM;

    c2_kernel<<<1, 512>>>(c);
    sln_kernel<<<rows / RR, TPB>>>(x, w, b, c, out, bkt, wb);
}